// round 1
// baseline (speedup 1.0000x reference)
#include <cuda_runtime.h>
#include <math.h>

// Problem constants
#define BDIM 4
#define SDIM 2048
#define DDIM 2048
#define HDIM 16
#define DKDIM 128
#define MDIM (BDIM * SDIM)   // 8192

#define NEGV (-1e9f)
#define SCALE 0.08838834764831845f  // 1/sqrt(128)

// Scratch (device globals — no cudaMalloc allowed)
__device__ float g_Q[(size_t)MDIM * DDIM];
__device__ float g_K[(size_t)MDIM * DDIM];
__device__ float g_V[(size_t)MDIM * DDIM];
__device__ float g_att[(size_t)MDIM * DDIM];
__device__ float g_vmean[BDIM * HDIM * DKDIM];

// ---------------------------------------------------------------------------
// SGEMM (TN): C[m,n] = sum_k A[m,k] * W[n,k].  A:[M,K] row-major, W:[N,K] row-major.
// 128x128 block tile, BK=16, 256 threads, 8x8 per-thread micro-tile.
// ---------------------------------------------------------------------------
__global__ __launch_bounds__(256) void sgemm_tn_kernel(
    const float* __restrict__ A, const float* __restrict__ W,
    float* __restrict__ C, int M, int N, int K)
{
    __shared__ float As[16][132];
    __shared__ float Ws[16][132];

    const int tid = threadIdx.x;
    const int bm = blockIdx.y * 128;
    const int bn = blockIdx.x * 128;
    const int tx = tid & 15;
    const int ty = tid >> 4;
    const int lr = tid >> 2;          // 0..63
    const int lc = (tid & 3) * 4;     // 0,4,8,12

    const float* Ap = A + (size_t)(bm + lr) * K + lc;
    const float* Wp = W + (size_t)(bn + lr) * K + lc;

    float acc[8][8];
#pragma unroll
    for (int i = 0; i < 8; i++)
#pragma unroll
        for (int j = 0; j < 8; j++) acc[i][j] = 0.f;

    for (int k0 = 0; k0 < K; k0 += 16) {
        float4 a0 = *(const float4*)(Ap + k0);
        float4 a1 = *(const float4*)(Ap + (size_t)64 * K + k0);
        float4 w0 = *(const float4*)(Wp + k0);
        float4 w1 = *(const float4*)(Wp + (size_t)64 * K + k0);
        __syncthreads();
        As[lc + 0][lr] = a0.x; As[lc + 1][lr] = a0.y;
        As[lc + 2][lr] = a0.z; As[lc + 3][lr] = a0.w;
        As[lc + 0][lr + 64] = a1.x; As[lc + 1][lr + 64] = a1.y;
        As[lc + 2][lr + 64] = a1.z; As[lc + 3][lr + 64] = a1.w;
        Ws[lc + 0][lr] = w0.x; Ws[lc + 1][lr] = w0.y;
        Ws[lc + 2][lr] = w0.z; Ws[lc + 3][lr] = w0.w;
        Ws[lc + 0][lr + 64] = w1.x; Ws[lc + 1][lr + 64] = w1.y;
        Ws[lc + 2][lr + 64] = w1.z; Ws[lc + 3][lr + 64] = w1.w;
        __syncthreads();
#pragma unroll
        for (int kk = 0; kk < 16; kk++) {
            float ar[8], wr[8];
            *(float4*)&ar[0] = *(const float4*)&As[kk][ty * 8];
            *(float4*)&ar[4] = *(const float4*)&As[kk][ty * 8 + 4];
            *(float4*)&wr[0] = *(const float4*)&Ws[kk][tx * 8];
            *(float4*)&wr[4] = *(const float4*)&Ws[kk][tx * 8 + 4];
#pragma unroll
            for (int i = 0; i < 8; i++)
#pragma unroll
                for (int j = 0; j < 8; j++)
                    acc[i][j] += ar[i] * wr[j];
        }
    }

#pragma unroll
    for (int i = 0; i < 8; i++) {
        float* Crow = C + (size_t)(bm + ty * 8 + i) * N + bn + tx * 8;
        *(float4*)Crow = make_float4(acc[i][0], acc[i][1], acc[i][2], acc[i][3]);
        *(float4*)(Crow + 4) = make_float4(acc[i][4], acc[i][5], acc[i][6], acc[i][7]);
    }
}

// ---------------------------------------------------------------------------
// Per-(b,h) mean of V over sequence (for fully-masked-row uniform softmax).
// ---------------------------------------------------------------------------
__global__ void vmean_kernel(const float* __restrict__ Vg, float* __restrict__ vmean)
{
    int bh = blockIdx.x;                 // 0..63  (b*16 + h)
    int b = bh >> 4, h = bh & 15;
    int d = threadIdx.x;                 // 0..127
    const float* Vb = Vg + ((size_t)b * SDIM) * DDIM + h * DKDIM + d;
    float s = 0.f;
    for (int j = 0; j < SDIM; j++) s += Vb[(size_t)j * DDIM];
    vmean[bh * DKDIM + d] = s * (1.f / (float)SDIM);
}

// ---------------------------------------------------------------------------
// Flash attention (fp32, causal + key-padding with literal -1e9 semantics).
// Block = 256 threads handles 64 queries of one (b,h); loops over key tiles of 64.
// SMEM: Qs[64][132] | union(Kt[128][68], Vs[64][132]) | S[64][65] | row state.
// ---------------------------------------------------------------------------
#define ATTN_SMEM_FLOATS (8448 + 8704 + 4160 + 192)
#define ATTN_SMEM_BYTES (ATTN_SMEM_FLOATS * 4)

__global__ __launch_bounds__(256) void attn_kernel(
    const float* __restrict__ Qg, const float* __restrict__ Kg,
    const float* __restrict__ Vg, const int* __restrict__ mask,
    const float* __restrict__ vmean, float* __restrict__ Og)
{
    extern __shared__ float sm[];
    float* Qs   = sm;                       // [64][132]
    float* KVs  = sm + 8448;                // Kt[128][68] then Vs[64][132]
    float* Ss   = sm + 8448 + 8704;         // [64][65]
    float* rowm = Ss + 64 * 65;             // [64]
    float* rowl = rowm + 64;                // [64]
    float* rowc = rowl + 64;                // [64]

    const int qt = blockIdx.x;   // 0..31
    const int h  = blockIdx.y;   // 0..15
    const int b  = blockIdx.z;   // 0..3
    const int tid = threadIdx.x;
    const int q0 = qt * 64;

    const size_t base = ((size_t)b * SDIM) * DDIM + (size_t)h * DKDIM;
    const float* Qb = Qg + base;
    const float* Kb = Kg + base;
    const float* Vb = Vg + base;
    const int* mb = mask + b * SDIM;

    // Load Q tile [64 x 128] -> Qs (row stride 132)
    for (int i = tid; i < 64 * 32; i += 256) {
        int r = i >> 5, c4 = (i & 31) * 4;
        float4 v = *(const float4*)(Qb + (size_t)(q0 + r) * DDIM + c4);
        float* dst = Qs + r * 132 + c4;
        dst[0] = v.x; dst[1] = v.y; dst[2] = v.z; dst[3] = v.w;
    }
    if (tid < 64) { rowm[tid] = -3.402823466e38f; rowl[tid] = 0.f; rowc[tid] = 0.f; }

    const int sy = tid >> 4;        // 0..15 : score rows sy*4..+3
    const int sx = tid & 15;        // 0..15 : score cols sx*4..+3
    const int r0 = sy * 4;          // PV row base
    const int d0 = sx * 4;          // PV d-chunk bases: d0 and 64+d0

    float o[4][8];
#pragma unroll
    for (int r = 0; r < 4; r++)
#pragma unroll
        for (int u = 0; u < 8; u++) o[r][u] = 0.f;

    for (int kt = 0; kt <= qt; kt++) {
        const int k0 = kt * 64;
        __syncthreads();  // protect KVs (prev PV reads) before K store

        // Load K tile transposed: Kt[d][j], stride 68
        for (int i = tid; i < 64 * 32; i += 256) {
            int j = i >> 5, c4 = (i & 31) * 4;
            float4 v = *(const float4*)(Kb + (size_t)(k0 + j) * DDIM + c4);
            KVs[(c4 + 0) * 68 + j] = v.x;
            KVs[(c4 + 1) * 68 + j] = v.y;
            KVs[(c4 + 2) * 68 + j] = v.z;
            KVs[(c4 + 3) * 68 + j] = v.w;
        }
        __syncthreads();

        // Score phase: accm[r][c] = Q[q0+sy*4+r] . K[k0+sx*4+c]
        {
            float accm[4][4];
#pragma unroll
            for (int r = 0; r < 4; r++)
#pragma unroll
                for (int c = 0; c < 4; c++) accm[r][c] = 0.f;

            const float* qrow0 = Qs + (sy * 4 + 0) * 132;
            const float* qrow1 = Qs + (sy * 4 + 1) * 132;
            const float* qrow2 = Qs + (sy * 4 + 2) * 132;
            const float* qrow3 = Qs + (sy * 4 + 3) * 132;
#pragma unroll 4
            for (int d = 0; d < 128; d++) {
                float4 kv = *(const float4*)&KVs[d * 68 + sx * 4];
                float q0v = qrow0[d], q1v = qrow1[d], q2v = qrow2[d], q3v = qrow3[d];
                accm[0][0] += q0v * kv.x; accm[0][1] += q0v * kv.y;
                accm[0][2] += q0v * kv.z; accm[0][3] += q0v * kv.w;
                accm[1][0] += q1v * kv.x; accm[1][1] += q1v * kv.y;
                accm[1][2] += q1v * kv.z; accm[1][3] += q1v * kv.w;
                accm[2][0] += q2v * kv.x; accm[2][1] += q2v * kv.y;
                accm[2][2] += q2v * kv.z; accm[2][3] += q2v * kv.w;
                accm[3][0] += q3v * kv.x; accm[3][1] += q3v * kv.y;
                accm[3][2] += q3v * kv.z; accm[3][3] += q3v * kv.w;
            }

            bool padok[4];
            int gj[4];
#pragma unroll
            for (int c = 0; c < 4; c++) {
                gj[c] = k0 + sx * 4 + c;
                padok[c] = (mb[gj[c]] != 0);
            }
#pragma unroll
            for (int r = 0; r < 4; r++) {
                int gi = q0 + sy * 4 + r;
#pragma unroll
                for (int c = 0; c < 4; c++) {
                    float s = (gj[c] <= gi && padok[c]) ? accm[r][c] * SCALE : NEGV;
                    Ss[(sy * 4 + r) * 65 + sx * 4 + c] = s;
                }
            }
        }
        __syncthreads();

        // V load (overwrites Kt — safe, K reads done) + online softmax in parallel
        for (int i = tid; i < 64 * 32; i += 256) {
            int j = i >> 5, c4 = (i & 31) * 4;
            float4 v = *(const float4*)(Vb + (size_t)(k0 + j) * DDIM + c4);
            float* dst = KVs + j * 132 + c4;
            dst[0] = v.x; dst[1] = v.y; dst[2] = v.z; dst[3] = v.w;
        }
        {
            int row = tid >> 2;
            int c0 = (tid & 3) * 16;
            float* srow = Ss + row * 65 + c0;
            float mloc = -3.402823466e38f;
#pragma unroll
            for (int k = 0; k < 16; k++) mloc = fmaxf(mloc, srow[k]);
            mloc = fmaxf(mloc, __shfl_xor_sync(0xffffffffu, mloc, 1));
            mloc = fmaxf(mloc, __shfl_xor_sync(0xffffffffu, mloc, 2));
            float mold = rowm[row];
            float mnew = fmaxf(mold, mloc);
            float lsum = 0.f;
#pragma unroll
            for (int k = 0; k < 16; k++) {
                float e = __expf(srow[k] - mnew);
                srow[k] = e;
                lsum += e;
            }
            lsum += __shfl_xor_sync(0xffffffffu, lsum, 1);
            lsum += __shfl_xor_sync(0xffffffffu, lsum, 2);
            if ((tid & 3) == 0) {
                float corr = __expf(mold - mnew);
                rowm[row] = mnew;
                rowl[row] = rowl[row] * corr + lsum;
                rowc[row] = corr;
            }
        }
        __syncthreads();

        // PV phase: o[r][*] = o[r][*]*corr + sum_j P[r][j] * V[j][*]
        {
            float c0v = rowc[r0 + 0], c1v = rowc[r0 + 1];
            float c2v = rowc[r0 + 2], c3v = rowc[r0 + 3];
#pragma unroll
            for (int u = 0; u < 8; u++) {
                o[0][u] *= c0v; o[1][u] *= c1v; o[2][u] *= c2v; o[3][u] *= c3v;
            }
            const float* p0 = Ss + (r0 + 0) * 65;
            const float* p1 = Ss + (r0 + 1) * 65;
            const float* p2 = Ss + (r0 + 2) * 65;
            const float* p3 = Ss + (r0 + 3) * 65;
#pragma unroll 2
            for (int j = 0; j < 64; j++) {
                float4 va = *(const float4*)&KVs[j * 132 + d0];
                float4 vb = *(const float4*)&KVs[j * 132 + 64 + d0];
                float w0 = p0[j], w1 = p1[j], w2 = p2[j], w3 = p3[j];
                o[0][0] += w0 * va.x; o[0][1] += w0 * va.y; o[0][2] += w0 * va.z; o[0][3] += w0 * va.w;
                o[0][4] += w0 * vb.x; o[0][5] += w0 * vb.y; o[0][6] += w0 * vb.z; o[0][7] += w0 * vb.w;
                o[1][0] += w1 * va.x; o[1][1] += w1 * va.y; o[1][2] += w1 * va.z; o[1][3] += w1 * va.w;
                o[1][4] += w1 * vb.x; o[1][5] += w1 * vb.y; o[1][6] += w1 * vb.z; o[1][7] += w1 * vb.w;
                o[2][0] += w2 * va.x; o[2][1] += w2 * va.y; o[2][2] += w2 * va.z; o[2][3] += w2 * va.w;
                o[2][4] += w2 * vb.x; o[2][5] += w2 * vb.y; o[2][6] += w2 * vb.z; o[2][7] += w2 * vb.w;
                o[3][0] += w3 * va.x; o[3][1] += w3 * va.y; o[3][2] += w3 * va.z; o[3][3] += w3 * va.w;
                o[3][4] += w3 * vb.x; o[3][5] += w3 * vb.y; o[3][6] += w3 * vb.z; o[3][7] += w3 * vb.w;
            }
        }
    }

    // Epilogue: normalize or substitute uniform-softmax (V mean) for fully-masked rows
    {
        const float* vm = vmean + ((size_t)b * HDIM + h) * DKDIM;
#pragma unroll
        for (int r = 0; r < 4; r++) {
            int gi = q0 + r0 + r;
            float m = rowm[r0 + r];
            float inv = 1.f / rowl[r0 + r];
            float* dst = Og + ((size_t)b * SDIM + gi) * DDIM + h * DKDIM;
            float4 ra, rb;
            if (m > -1e8f) {
                ra = make_float4(o[r][0] * inv, o[r][1] * inv, o[r][2] * inv, o[r][3] * inv);
                rb = make_float4(o[r][4] * inv, o[r][5] * inv, o[r][6] * inv, o[r][7] * inv);
            } else {
                ra = *(const float4*)(vm + d0);
                rb = *(const float4*)(vm + 64 + d0);
            }
            *(float4*)(dst + d0) = ra;
            *(float4*)(dst + 64 + d0) = rb;
        }
    }
}

// ---------------------------------------------------------------------------
extern "C" void kernel_launch(void* const* d_in, const int* in_sizes, int n_in,
                              void* d_out, int out_size)
{
    const float* x    = (const float*)d_in[0];
    const int*   mask = (const int*)d_in[1];
    const float* wq   = (const float*)d_in[2];
    const float* wk   = (const float*)d_in[3];
    const float* wv   = (const float*)d_in[4];
    const float* wo   = (const float*)d_in[5];
    float* out = (float*)d_out;

    float *pQ, *pK, *pV, *pAtt, *pVm;
    cudaGetSymbolAddress((void**)&pQ, g_Q);
    cudaGetSymbolAddress((void**)&pK, g_K);
    cudaGetSymbolAddress((void**)&pV, g_V);
    cudaGetSymbolAddress((void**)&pAtt, g_att);
    cudaGetSymbolAddress((void**)&pVm, g_vmean);

    cudaFuncSetAttribute(attn_kernel, cudaFuncAttributeMaxDynamicSharedMemorySize,
                         ATTN_SMEM_BYTES);

    dim3 gg(DDIM / 128, MDIM / 128);  // (16, 64)
    sgemm_tn_kernel<<<gg, 256>>>(x, wq, pQ, MDIM, DDIM, DDIM);
    sgemm_tn_kernel<<<gg, 256>>>(x, wk, pK, MDIM, DDIM, DDIM);
    sgemm_tn_kernel<<<gg, 256>>>(x, wv, pV, MDIM, DDIM, DDIM);

    vmean_kernel<<<BDIM * HDIM, DKDIM>>>(pV, pVm);

    attn_kernel<<<dim3(SDIM / 64, HDIM, BDIM), 256, ATTN_SMEM_BYTES>>>(
        pQ, pK, pV, mask, pVm, pAtt);

    sgemm_tn_kernel<<<gg, 256>>>(pAtt, wo, out, MDIM, DDIM, DDIM);
}

// round 3
// speedup vs baseline: 1.2040x; 1.2040x over previous
#include <cuda_runtime.h>
#include <cstdint>
#include <math.h>

// Problem constants
#define BDIM 4
#define SDIM 2048
#define DDIM 2048
#define HDIM 16
#define DKDIM 128
#define MDIM (BDIM * SDIM)   // 8192

#define NEGV (-1e9f)
#define SCALE 0.08838834764831845f  // 1/sqrt(128)

// Scratch (device globals — no cudaMalloc allowed)
__device__ float g_Q[(size_t)MDIM * DDIM];
__device__ float g_K[(size_t)MDIM * DDIM];
__device__ float g_V[(size_t)MDIM * DDIM];
__device__ float g_att[(size_t)MDIM * DDIM];
__device__ float g_vmean[BDIM * HDIM * DKDIM];

// ===========================================================================
// Tensor-core GEMM via mma.sync (tf32), TN: C[m,n] = sum_k A[m,k] * W[n,k]
// CTA tile 128x128, 8 warps (4m x 2n), warp tile 32x64, K chunk 32.
// ===========================================================================
#define GK 2048
#define GN 2048

__device__ __forceinline__ float cvt_tf32(float x) {
    float r;
    asm("cvt.rna.tf32.f32 %0, %1;" : "=f"(r) : "f"(x));
    return r;
}

__device__ __forceinline__ void mma_tf32_16x8x8(
    float* c, uint32_t a0, uint32_t a1, uint32_t a2, uint32_t a3,
    uint32_t b0, uint32_t b1)
{
    asm volatile(
        "mma.sync.aligned.m16n8k8.row.col.f32.tf32.tf32.f32 "
        "{%0,%1,%2,%3}, {%4,%5,%6,%7}, {%8,%9}, {%0,%1,%2,%3};"
        : "+f"(c[0]), "+f"(c[1]), "+f"(c[2]), "+f"(c[3])
        : "r"(a0), "r"(a1), "r"(a2), "r"(a3), "r"(b0), "r"(b1));
}

__global__ __launch_bounds__(256) void gemm_mma_kernel(
    const float* __restrict__ A, const float* __restrict__ W, float* __restrict__ C)
{
    __shared__ float As[128][36];
    __shared__ float Ws[128][36];

    const int tid  = threadIdx.x;
    const int lane = tid & 31;
    const int w    = tid >> 5;
    const int wm   = (w & 3) * 32;   // warp m offset in tile
    const int wn   = (w >> 2) * 64;  // warp n offset in tile
    const int gid  = lane >> 2;      // 0..7
    const int tig  = lane & 3;       // 0..3
    const int bm   = blockIdx.y * 128;
    const int bn   = blockIdx.x * 128;

    const int r0  = tid >> 3;        // 0..31 (row base for staging)
    const int c0  = (tid & 7) * 4;   // 0..28 (k column base)

    const float* Ap = A + (size_t)(bm + r0) * GK + c0;
    const float* Wp = W + (size_t)(bn + r0) * GK + c0;

    float acc[2][8][4];
#pragma unroll
    for (int mt = 0; mt < 2; mt++)
#pragma unroll
        for (int nt = 0; nt < 8; nt++)
#pragma unroll
            for (int q = 0; q < 4; q++) acc[mt][nt][q] = 0.f;

    float4 av[4], wv[4];

    // Prologue: load K-chunk 0
#pragma unroll
    for (int j = 0; j < 4; j++) {
        av[j] = *(const float4*)(Ap + (size_t)(32 * j) * GK);
        wv[j] = *(const float4*)(Wp + (size_t)(32 * j) * GK);
    }
#pragma unroll
    for (int j = 0; j < 4; j++) {
        float* da = &As[r0 + 32 * j][c0];
        da[0] = cvt_tf32(av[j].x); da[1] = cvt_tf32(av[j].y);
        da[2] = cvt_tf32(av[j].z); da[3] = cvt_tf32(av[j].w);
        float* dw = &Ws[r0 + 32 * j][c0];
        dw[0] = cvt_tf32(wv[j].x); dw[1] = cvt_tf32(wv[j].y);
        dw[2] = cvt_tf32(wv[j].z); dw[3] = cvt_tf32(wv[j].w);
    }
    __syncthreads();

    const int NKC = GK / 32;  // 64
    for (int kc = 0; kc < NKC; kc++) {
        // Prefetch next K-chunk into registers (overlaps with compute below)
        if (kc + 1 < NKC) {
            const float* Ap2 = Ap + (kc + 1) * 32;
            const float* Wp2 = Wp + (kc + 1) * 32;
#pragma unroll
            for (int j = 0; j < 4; j++) {
                av[j] = *(const float4*)(Ap2 + (size_t)(32 * j) * GK);
                wv[j] = *(const float4*)(Wp2 + (size_t)(32 * j) * GK);
            }
        }

        // Compute: 4 k8-steps over the 32-wide chunk
#pragma unroll
        for (int ks = 0; ks < 4; ks++) {
            const int kk = ks * 8;
            uint32_t a[2][4];
#pragma unroll
            for (int mt = 0; mt < 2; mt++) {
                const int rb = wm + mt * 16;
                a[mt][0] = __float_as_uint(As[rb + gid][kk + tig]);
                a[mt][1] = __float_as_uint(As[rb + gid + 8][kk + tig]);
                a[mt][2] = __float_as_uint(As[rb + gid][kk + tig + 4]);
                a[mt][3] = __float_as_uint(As[rb + gid + 8][kk + tig + 4]);
            }
#pragma unroll
            for (int nt = 0; nt < 8; nt++) {
                const int nb = wn + nt * 8 + gid;
                uint32_t b0 = __float_as_uint(Ws[nb][kk + tig]);
                uint32_t b1 = __float_as_uint(Ws[nb][kk + tig + 4]);
                mma_tf32_16x8x8(acc[0][nt], a[0][0], a[0][1], a[0][2], a[0][3], b0, b1);
                mma_tf32_16x8x8(acc[1][nt], a[1][0], a[1][1], a[1][2], a[1][3], b0, b1);
            }
        }
        __syncthreads();

        if (kc + 1 < NKC) {
#pragma unroll
            for (int j = 0; j < 4; j++) {
                float* da = &As[r0 + 32 * j][c0];
                da[0] = cvt_tf32(av[j].x); da[1] = cvt_tf32(av[j].y);
                da[2] = cvt_tf32(av[j].z); da[3] = cvt_tf32(av[j].w);
                float* dw = &Ws[r0 + 32 * j][c0];
                dw[0] = cvt_tf32(wv[j].x); dw[1] = cvt_tf32(wv[j].y);
                dw[2] = cvt_tf32(wv[j].z); dw[3] = cvt_tf32(wv[j].w);
            }
            __syncthreads();
        }
    }

    // Epilogue: direct stores from fragment layout
#pragma unroll
    for (int mt = 0; mt < 2; mt++) {
        const int row = bm + wm + mt * 16 + gid;
#pragma unroll
        for (int nt = 0; nt < 8; nt++) {
            const int col = bn + wn + nt * 8 + tig * 2;
            *(float2*)(C + (size_t)row * GN + col) =
                make_float2(acc[mt][nt][0], acc[mt][nt][1]);
            *(float2*)(C + (size_t)(row + 8) * GN + col) =
                make_float2(acc[mt][nt][2], acc[mt][nt][3]);
        }
    }
}

// ---------------------------------------------------------------------------
// Per-(b,h) mean of V over sequence (for fully-masked-row uniform softmax).
// ---------------------------------------------------------------------------
__global__ void vmean_kernel(const float* __restrict__ Vg, float* __restrict__ vmean)
{
    int bh = blockIdx.x;                 // 0..63  (b*16 + h)
    int b = bh >> 4, h = bh & 15;
    int d = threadIdx.x;                 // 0..127
    const float* Vb = Vg + ((size_t)b * SDIM) * DDIM + h * DKDIM + d;
    float s = 0.f;
    for (int j = 0; j < SDIM; j++) s += Vb[(size_t)j * DDIM];
    vmean[bh * DKDIM + d] = s * (1.f / (float)SDIM);
}

// ---------------------------------------------------------------------------
// Flash attention (fp32, causal + key-padding with literal -1e9 semantics).
// Block = 256 threads handles 64 queries of one (b,h); loops over key tiles of 64.
// ---------------------------------------------------------------------------
#define ATTN_SMEM_FLOATS (8448 + 8704 + 4160 + 192)
#define ATTN_SMEM_BYTES (ATTN_SMEM_FLOATS * 4)

__global__ __launch_bounds__(256) void attn_kernel(
    const float* __restrict__ Qg, const float* __restrict__ Kg,
    const float* __restrict__ Vg, const int* __restrict__ mask,
    const float* __restrict__ vmean, float* __restrict__ Og)
{
    extern __shared__ float sm[];
    float* Qs   = sm;                       // [64][132]
    float* KVs  = sm + 8448;                // Kt[128][68] then Vs[64][132]
    float* Ss   = sm + 8448 + 8704;         // [64][65]
    float* rowm = Ss + 64 * 65;             // [64]
    float* rowl = rowm + 64;                // [64]
    float* rowc = rowl + 64;                // [64]

    const int qt = blockIdx.x;   // 0..31
    const int h  = blockIdx.y;   // 0..15
    const int b  = blockIdx.z;   // 0..3
    const int tid = threadIdx.x;
    const int q0 = qt * 64;

    const size_t base = ((size_t)b * SDIM) * DDIM + (size_t)h * DKDIM;
    const float* Qb = Qg + base;
    const float* Kb = Kg + base;
    const float* Vb = Vg + base;
    const int* mb = mask + b * SDIM;

    for (int i = tid; i < 64 * 32; i += 256) {
        int r = i >> 5, c4 = (i & 31) * 4;
        float4 v = *(const float4*)(Qb + (size_t)(q0 + r) * DDIM + c4);
        float* dst = Qs + r * 132 + c4;
        dst[0] = v.x; dst[1] = v.y; dst[2] = v.z; dst[3] = v.w;
    }
    if (tid < 64) { rowm[tid] = -3.402823466e38f; rowl[tid] = 0.f; rowc[tid] = 0.f; }

    const int sy = tid >> 4;
    const int sx = tid & 15;
    const int r0 = sy * 4;
    const int d0 = sx * 4;

    float o[4][8];
#pragma unroll
    for (int r = 0; r < 4; r++)
#pragma unroll
        for (int u = 0; u < 8; u++) o[r][u] = 0.f;

    for (int kt = 0; kt <= qt; kt++) {
        const int k0 = kt * 64;
        __syncthreads();

        for (int i = tid; i < 64 * 32; i += 256) {
            int j = i >> 5, c4 = (i & 31) * 4;
            float4 v = *(const float4*)(Kb + (size_t)(k0 + j) * DDIM + c4);
            KVs[(c4 + 0) * 68 + j] = v.x;
            KVs[(c4 + 1) * 68 + j] = v.y;
            KVs[(c4 + 2) * 68 + j] = v.z;
            KVs[(c4 + 3) * 68 + j] = v.w;
        }
        __syncthreads();

        {
            float accm[4][4];
#pragma unroll
            for (int r = 0; r < 4; r++)
#pragma unroll
                for (int c = 0; c < 4; c++) accm[r][c] = 0.f;

            const float* qrow0 = Qs + (sy * 4 + 0) * 132;
            const float* qrow1 = Qs + (sy * 4 + 1) * 132;
            const float* qrow2 = Qs + (sy * 4 + 2) * 132;
            const float* qrow3 = Qs + (sy * 4 + 3) * 132;
#pragma unroll 4
            for (int d = 0; d < 128; d++) {
                float4 kv = *(const float4*)&KVs[d * 68 + sx * 4];
                float q0v = qrow0[d], q1v = qrow1[d], q2v = qrow2[d], q3v = qrow3[d];
                accm[0][0] += q0v * kv.x; accm[0][1] += q0v * kv.y;
                accm[0][2] += q0v * kv.z; accm[0][3] += q0v * kv.w;
                accm[1][0] += q1v * kv.x; accm[1][1] += q1v * kv.y;
                accm[1][2] += q1v * kv.z; accm[1][3] += q1v * kv.w;
                accm[2][0] += q2v * kv.x; accm[2][1] += q2v * kv.y;
                accm[2][2] += q2v * kv.z; accm[2][3] += q2v * kv.w;
                accm[3][0] += q3v * kv.x; accm[3][1] += q3v * kv.y;
                accm[3][2] += q3v * kv.z; accm[3][3] += q3v * kv.w;
            }

            bool padok[4];
            int gj[4];
#pragma unroll
            for (int c = 0; c < 4; c++) {
                gj[c] = k0 + sx * 4 + c;
                padok[c] = (mb[gj[c]] != 0);
            }
#pragma unroll
            for (int r = 0; r < 4; r++) {
                int gi = q0 + sy * 4 + r;
#pragma unroll
                for (int c = 0; c < 4; c++) {
                    float s = (gj[c] <= gi && padok[c]) ? accm[r][c] * SCALE : NEGV;
                    Ss[(sy * 4 + r) * 65 + sx * 4 + c] = s;
                }
            }
        }
        __syncthreads();

        for (int i = tid; i < 64 * 32; i += 256) {
            int j = i >> 5, c4 = (i & 31) * 4;
            float4 v = *(const float4*)(Vb + (size_t)(k0 + j) * DDIM + c4);
            float* dst = KVs + j * 132 + c4;
            dst[0] = v.x; dst[1] = v.y; dst[2] = v.z; dst[3] = v.w;
        }
        {
            int row = tid >> 2;
            int c0 = (tid & 3) * 16;
            float* srow = Ss + row * 65 + c0;
            float mloc = -3.402823466e38f;
#pragma unroll
            for (int k = 0; k < 16; k++) mloc = fmaxf(mloc, srow[k]);
            mloc = fmaxf(mloc, __shfl_xor_sync(0xffffffffu, mloc, 1));
            mloc = fmaxf(mloc, __shfl_xor_sync(0xffffffffu, mloc, 2));
            float mold = rowm[row];
            float mnew = fmaxf(mold, mloc);
            float lsum = 0.f;
#pragma unroll
            for (int k = 0; k < 16; k++) {
                float e = __expf(srow[k] - mnew);
                srow[k] = e;
                lsum += e;
            }
            lsum += __shfl_xor_sync(0xffffffffu, lsum, 1);
            lsum += __shfl_xor_sync(0xffffffffu, lsum, 2);
            if ((tid & 3) == 0) {
                float corr = __expf(mold - mnew);
                rowm[row] = mnew;
                rowl[row] = rowl[row] * corr + lsum;
                rowc[row] = corr;
            }
        }
        __syncthreads();

        {
            float c0v = rowc[r0 + 0], c1v = rowc[r0 + 1];
            float c2v = rowc[r0 + 2], c3v = rowc[r0 + 3];
#pragma unroll
            for (int u = 0; u < 8; u++) {
                o[0][u] *= c0v; o[1][u] *= c1v; o[2][u] *= c2v; o[3][u] *= c3v;
            }
            const float* p0 = Ss + (r0 + 0) * 65;
            const float* p1 = Ss + (r0 + 1) * 65;
            const float* p2 = Ss + (r0 + 2) * 65;
            const float* p3 = Ss + (r0 + 3) * 65;
#pragma unroll 2
            for (int j = 0; j < 64; j++) {
                float4 va = *(const float4*)&KVs[j * 132 + d0];
                float4 vb = *(const float4*)&KVs[j * 132 + 64 + d0];
                float w0 = p0[j], w1 = p1[j], w2 = p2[j], w3 = p3[j];
                o[0][0] += w0 * va.x; o[0][1] += w0 * va.y; o[0][2] += w0 * va.z; o[0][3] += w0 * va.w;
                o[0][4] += w0 * vb.x; o[0][5] += w0 * vb.y; o[0][6] += w0 * vb.z; o[0][7] += w0 * vb.w;
                o[1][0] += w1 * va.x; o[1][1] += w1 * va.y; o[1][2] += w1 * va.z; o[1][3] += w1 * va.w;
                o[1][4] += w1 * vb.x; o[1][5] += w1 * vb.y; o[1][6] += w1 * vb.z; o[1][7] += w1 * vb.w;
                o[2][0] += w2 * va.x; o[2][1] += w2 * va.y; o[2][2] += w2 * va.z; o[2][3] += w2 * va.w;
                o[2][4] += w2 * vb.x; o[2][5] += w2 * vb.y; o[2][6] += w2 * vb.z; o[2][7] += w2 * vb.w;
                o[3][0] += w3 * va.x; o[3][1] += w3 * va.y; o[3][2] += w3 * va.z; o[3][3] += w3 * va.w;
                o[3][4] += w3 * vb.x; o[3][5] += w3 * vb.y; o[3][6] += w3 * vb.z; o[3][7] += w3 * vb.w;
            }
        }
    }

    {
        const float* vm = vmean + ((size_t)b * HDIM + h) * DKDIM;
#pragma unroll
        for (int r = 0; r < 4; r++) {
            int gi = q0 + r0 + r;
            float m = rowm[r0 + r];
            float inv = 1.f / rowl[r0 + r];
            float* dst = Og + ((size_t)b * SDIM + gi) * DDIM + h * DKDIM;
            float4 ra, rb;
            if (m > -1e8f) {
                ra = make_float4(o[r][0] * inv, o[r][1] * inv, o[r][2] * inv, o[r][3] * inv);
                rb = make_float4(o[r][4] * inv, o[r][5] * inv, o[r][6] * inv, o[r][7] * inv);
            } else {
                ra = *(const float4*)(vm + d0);
                rb = *(const float4*)(vm + 64 + d0);
            }
            *(float4*)(dst + d0) = ra;
            *(float4*)(dst + 64 + d0) = rb;
        }
    }
}

// ---------------------------------------------------------------------------
extern "C" void kernel_launch(void* const* d_in, const int* in_sizes, int n_in,
                              void* d_out, int out_size)
{
    const float* x    = (const float*)d_in[0];
    const int*   mask = (const int*)d_in[1];
    const float* wq   = (const float*)d_in[2];
    const float* wk   = (const float*)d_in[3];
    const float* wv   = (const float*)d_in[4];
    const float* wo   = (const float*)d_in[5];
    float* out = (float*)d_out;

    float *pQ, *pK, *pV, *pAtt, *pVm;
    cudaGetSymbolAddress((void**)&pQ, g_Q);
    cudaGetSymbolAddress((void**)&pK, g_K);
    cudaGetSymbolAddress((void**)&pV, g_V);
    cudaGetSymbolAddress((void**)&pAtt, g_att);
    cudaGetSymbolAddress((void**)&pVm, g_vmean);

    cudaFuncSetAttribute(attn_kernel, cudaFuncAttributeMaxDynamicSharedMemorySize,
                         ATTN_SMEM_BYTES);

    dim3 gg(GN / 128, MDIM / 128);  // (16, 64)
    gemm_mma_kernel<<<gg, 256>>>(x, wq, pQ);
    gemm_mma_kernel<<<gg, 256>>>(x, wk, pK);
    gemm_mma_kernel<<<gg, 256>>>(x, wv, pV);

    vmean_kernel<<<BDIM * HDIM, DKDIM>>>(pV, pVm);

    attn_kernel<<<dim3(SDIM / 64, HDIM, BDIM), 256, ATTN_SMEM_BYTES>>>(
        pQ, pK, pV, mask, pVm, pAtt);

    gemm_mma_kernel<<<gg, 256>>>(pAtt, wo, out);
}

// round 4
// speedup vs baseline: 2.4342x; 2.0217x over previous
#include <cuda_runtime.h>
#include <cstdint>
#include <math.h>

// Problem constants
#define BDIM 4
#define SDIM 2048
#define DDIM 2048
#define HDIM 16
#define DKDIM 128
#define MDIM (BDIM * SDIM)   // 8192
#define GK 2048
#define GN 2048

#define NEGV (-1e9f)
#define SCALE 0.08838834764831845f  // 1/sqrt(128)

// Scratch (device globals — no cudaMalloc allowed)
__device__ float g_Q[(size_t)MDIM * DDIM];
__device__ float g_K[(size_t)MDIM * DDIM];
__device__ float g_V[(size_t)MDIM * DDIM];
__device__ float g_att[(size_t)MDIM * DDIM];
__device__ float g_vmean[BDIM * HDIM * DKDIM];

// ---------------------------------------------------------------------------
// Helpers
// ---------------------------------------------------------------------------
__device__ __forceinline__ float cvt_tf32(float x) {
    float r;
    asm("cvt.rna.tf32.f32 %0, %1;" : "=f"(r) : "f"(x));
    return r;
}

__device__ __forceinline__ void mma_tf32_16x8x8(
    float* c, uint32_t a0, uint32_t a1, uint32_t a2, uint32_t a3,
    uint32_t b0, uint32_t b1)
{
    asm volatile(
        "mma.sync.aligned.m16n8k8.row.col.f32.tf32.tf32.f32 "
        "{%0,%1,%2,%3}, {%4,%5,%6,%7}, {%8,%9}, {%0,%1,%2,%3};"
        : "+f"(c[0]), "+f"(c[1]), "+f"(c[2]), "+f"(c[3])
        : "r"(a0), "r"(a1), "r"(a2), "r"(a3), "r"(b0), "r"(b1));
}

__device__ __forceinline__ void mma_bf16_16x8x16(
    float* c, const uint32_t* a, uint32_t b0, uint32_t b1)
{
    asm volatile(
        "mma.sync.aligned.m16n8k16.row.col.f32.bf16.bf16.f32 "
        "{%0,%1,%2,%3}, {%4,%5,%6,%7}, {%8,%9}, {%0,%1,%2,%3};"
        : "+f"(c[0]), "+f"(c[1]), "+f"(c[2]), "+f"(c[3])
        : "r"(a[0]), "r"(a[1]), "r"(a[2]), "r"(a[3]), "r"(b0), "r"(b1));
}

// Split a pair of fp32 into packed bf16 hi and packed bf16 lo (rn-even).
__device__ __forceinline__ void split2(float x, float y, uint32_t& hi, uint32_t& lo)
{
    uint32_t bx = __float_as_uint(x), by = __float_as_uint(y);
    uint32_t hx = (bx + 0x7FFFu + ((bx >> 16) & 1u)) >> 16;
    uint32_t hy = (by + 0x7FFFu + ((by >> 16) & 1u)) >> 16;
    hi = hx | (hy << 16);
    float lx = x - __uint_as_float(hx << 16);
    float ly = y - __uint_as_float(hy << 16);
    uint32_t blx = __float_as_uint(lx), bly = __float_as_uint(ly);
    uint32_t hlx = (blx + 0x7FFFu + ((blx >> 16) & 1u)) >> 16;
    uint32_t hly = (bly + 0x7FFFu + ((bly >> 16) & 1u)) >> 16;
    lo = hlx | (hly << 16);
}

// Fast exp on FMA pipe (avoids MUFU floor). Rel err ~2e-6 for x <= 0.
__device__ __forceinline__ float fexp(float x)
{
    float t = x * 1.4426950408889634f;
    t = fmaxf(t, -126.0f);
    float n = rintf(t);
    float f = t - n;
    float p = 0.0013333558f;
    p = fmaf(p, f, 0.0096181291f);
    p = fmaf(p, f, 0.0555041087f);
    p = fmaf(p, f, 0.2402265070f);
    p = fmaf(p, f, 0.6931471806f);
    p = fmaf(p, f, 1.0f);
    int e = (int)n;
    return __uint_as_float((uint32_t)((e + 127) << 23)) * p;
}

// ===========================================================================
// GEMM (TN) via split-bf16 mma: C = A @ W.T with near-fp32 accuracy.
// CTA tile 128x128, 8 warps (4m x 2n), warp tile 32x64, K chunk 32.
// ===========================================================================
__global__ void __launch_bounds__(256, 2) gemm_mma_kernel(
    const float* __restrict__ A, const float* __restrict__ W, float* __restrict__ C)
{
    __shared__ uint32_t Ahs[128][20];
    __shared__ uint32_t Als[128][20];
    __shared__ uint32_t Bhs[128][20];
    __shared__ uint32_t Bls[128][20];

    const int tid  = threadIdx.x;
    const int lane = tid & 31;
    const int w    = tid >> 5;
    const int wm   = (w & 3) * 32;
    const int wn   = (w >> 2) * 64;
    const int gid  = lane >> 2;
    const int tig  = lane & 3;
    const int bm   = blockIdx.y * 128;
    const int bn   = blockIdx.x * 128;

    const int r0   = tid >> 3;        // 0..31
    const int c0f  = (tid & 7) * 4;   // float col base
    const int c0u  = (tid & 7) * 2;   // uint col base

    const float* Ap = A + (size_t)(bm + r0) * GK + c0f;
    const float* Wp = W + (size_t)(bn + r0) * GK + c0f;

    float acc[2][8][4];
#pragma unroll
    for (int mt = 0; mt < 2; mt++)
#pragma unroll
        for (int nt = 0; nt < 8; nt++)
#pragma unroll
            for (int q = 0; q < 4; q++) acc[mt][nt][q] = 0.f;

    for (int kc = 0; kc < GK / 32; kc++) {
        __syncthreads();
        const float* Ak = Ap + kc * 32;
        const float* Wk = Wp + kc * 32;
#pragma unroll
        for (int j = 0; j < 4; j++) {
            float4 a = *(const float4*)(Ak + (size_t)(32 * j) * GK);
            uint32_t h0, l0, h1, l1;
            split2(a.x, a.y, h0, l0); split2(a.z, a.w, h1, l1);
            *(uint2*)&Ahs[r0 + 32 * j][c0u] = make_uint2(h0, h1);
            *(uint2*)&Als[r0 + 32 * j][c0u] = make_uint2(l0, l1);
            float4 b = *(const float4*)(Wk + (size_t)(32 * j) * GK);
            split2(b.x, b.y, h0, l0); split2(b.z, b.w, h1, l1);
            *(uint2*)&Bhs[r0 + 32 * j][c0u] = make_uint2(h0, h1);
            *(uint2*)&Bls[r0 + 32 * j][c0u] = make_uint2(l0, l1);
        }
        __syncthreads();

#pragma unroll
        for (int ks = 0; ks < 2; ks++) {
            const int kb = ks * 8;
            uint32_t ah[2][4], al[2][4];
#pragma unroll
            for (int mt = 0; mt < 2; mt++) {
                const int rb = wm + mt * 16;
                ah[mt][0] = Ahs[rb + gid][kb + tig];
                ah[mt][1] = Ahs[rb + gid + 8][kb + tig];
                ah[mt][2] = Ahs[rb + gid][kb + tig + 4];
                ah[mt][3] = Ahs[rb + gid + 8][kb + tig + 4];
                al[mt][0] = Als[rb + gid][kb + tig];
                al[mt][1] = Als[rb + gid + 8][kb + tig];
                al[mt][2] = Als[rb + gid][kb + tig + 4];
                al[mt][3] = Als[rb + gid + 8][kb + tig + 4];
            }
#pragma unroll
            for (int nt = 0; nt < 8; nt++) {
                const int nb = wn + nt * 8 + gid;
                uint32_t bh0 = Bhs[nb][kb + tig], bh1 = Bhs[nb][kb + tig + 4];
                uint32_t bl0 = Bls[nb][kb + tig], bl1 = Bls[nb][kb + tig + 4];
                mma_bf16_16x8x16(acc[0][nt], ah[0], bh0, bh1);
                mma_bf16_16x8x16(acc[1][nt], ah[1], bh0, bh1);
                mma_bf16_16x8x16(acc[0][nt], ah[0], bl0, bl1);
                mma_bf16_16x8x16(acc[1][nt], ah[1], bl0, bl1);
                mma_bf16_16x8x16(acc[0][nt], al[0], bh0, bh1);
                mma_bf16_16x8x16(acc[1][nt], al[1], bh0, bh1);
            }
        }
    }

#pragma unroll
    for (int mt = 0; mt < 2; mt++) {
        const int row = bm + wm + mt * 16 + gid;
#pragma unroll
        for (int nt = 0; nt < 8; nt++) {
            const int col = bn + wn + nt * 8 + tig * 2;
            *(float2*)(C + (size_t)row * GN + col) =
                make_float2(acc[mt][nt][0], acc[mt][nt][1]);
            *(float2*)(C + (size_t)(row + 8) * GN + col) =
                make_float2(acc[mt][nt][2], acc[mt][nt][3]);
        }
    }
}

// ---------------------------------------------------------------------------
// Per-(b,h) mean of V over sequence (for fully-masked-row uniform softmax).
// ---------------------------------------------------------------------------
__global__ void vmean_kernel(const float* __restrict__ Vg, float* __restrict__ vmean)
{
    int bh = blockIdx.x;
    int b = bh >> 4, h = bh & 15;
    int d = threadIdx.x;
    const float* Vb = Vg + ((size_t)b * SDIM) * DDIM + h * DKDIM + d;
    float s = 0.f;
    for (int j = 0; j < SDIM; j++) s += Vb[(size_t)j * DDIM];
    vmean[bh * DKDIM + d] = s * (1.f / (float)SDIM);
}

// ===========================================================================
// Flash attention via tf32 mma. Q-tile 64, key tiles 64, 8 warps.
// QK: warps 4m x 2n (warp 16q x 32k). PV: warps 4m x 2d (warp 16q x 64d).
// SMEM: Qf (packed A-frags) | KPs (K stride 132 / P stride 68) | Vs (stride 136)
//        | stats | mask.
// ===========================================================================
#define ATT_SMEM_FLOATS 25856
#define ATT_SMEM_BYTES (ATT_SMEM_FLOATS * 4)

__global__ void __launch_bounds__(256, 2) attn_mma_kernel(
    const float* __restrict__ Qg, const float* __restrict__ Kg,
    const float* __restrict__ Vg, const int* __restrict__ mask,
    const float* __restrict__ vmean, float* __restrict__ Og)
{
    extern __shared__ float sm[];
    float* Qf   = sm;                 // 8192: [4 mb][16 ks][32 lane][4]
    float* KPs  = sm + 8192;          // 8448: K[64][132] then P[64][68]
    float* Vs   = sm + 16640;         // 8704: V[64][136]
    float* rowm = sm + 25344;         // [64]
    float* rowl = rowm + 64;          // [64]
    float* rowc = rowl + 64;          // [64]
    float* pmx  = rowc + 64;          // [2][64]
    float* pls  = pmx + 128;          // [2][64]
    int*   maskS = (int*)(pls + 128); // [64]

    const int qt = blockIdx.x, h = blockIdx.y, b = blockIdx.z;
    const int tid = threadIdx.x, lane = tid & 31, w = tid >> 5;
    const int gid = lane >> 2, tig = lane & 3;
    const int wqm = (w & 3) * 16;     // warp m-offset (rows)
    const int wn  = w >> 2;           // QK n-half (keys 0-31 / 32-63)
    const int wd  = (w >> 2) * 64;    // PV d-half
    const int q0  = qt * 64;

    const size_t base = ((size_t)b * SDIM) * DDIM + (size_t)h * DKDIM;
    const float* Qb = Qg + base;
    const float* Kb = Kg + base;
    const float* Vb = Vg + base;
    const int* mb = mask + b * SDIM;

    // Stage Q (tf32) row-major into KPs, then repack into A-fragment layout Qf
    for (int i = tid; i < 2048; i += 256) {
        int r = i >> 5, c4 = (i & 31) * 4;
        float4 v = *(const float4*)(Qb + (size_t)(q0 + r) * DDIM + c4);
        v.x = cvt_tf32(v.x); v.y = cvt_tf32(v.y);
        v.z = cvt_tf32(v.z); v.w = cvt_tf32(v.w);
        *(float4*)&KPs[r * 132 + c4] = v;
    }
    if (tid < 64) { rowm[tid] = -3.402823466e38f; rowl[tid] = 0.f; }
    __syncthreads();
    {
        const int mblk = w & 3;
        const int ks0 = (w >> 2) * 8;
#pragma unroll
        for (int ks = ks0; ks < ks0 + 8; ks++) {
            float a0 = KPs[(mblk * 16 + gid) * 132 + ks * 8 + tig];
            float a1 = KPs[(mblk * 16 + gid + 8) * 132 + ks * 8 + tig];
            float a2 = KPs[(mblk * 16 + gid) * 132 + ks * 8 + tig + 4];
            float a3 = KPs[(mblk * 16 + gid + 8) * 132 + ks * 8 + tig + 4];
            *(float4*)&Qf[((mblk * 16 + ks) * 32 + lane) * 4] = make_float4(a0, a1, a2, a3);
        }
    }

    const int r1 = wqm + gid, r2 = wqm + gid + 8;

    float o[8][4];
#pragma unroll
    for (int nt = 0; nt < 8; nt++)
#pragma unroll
        for (int q = 0; q < 4; q++) o[nt][q] = 0.f;

    for (int kt = 0; kt <= qt; kt++) {
        const int k0 = kt * 64;
        __syncthreads();  // prev-iter smem reads (and Qf repack on iter 0) complete

        // Load K (stride 132), V (stride 136), mask
        for (int i = tid; i < 2048; i += 256) {
            int r = i >> 5, c4 = (i & 31) * 4;
            float4 kv = *(const float4*)(Kb + (size_t)(k0 + r) * DDIM + c4);
            kv.x = cvt_tf32(kv.x); kv.y = cvt_tf32(kv.y);
            kv.z = cvt_tf32(kv.z); kv.w = cvt_tf32(kv.w);
            *(float4*)&KPs[r * 132 + c4] = kv;
            float4 vv = *(const float4*)(Vb + (size_t)(k0 + r) * DDIM + c4);
            vv.x = cvt_tf32(vv.x); vv.y = cvt_tf32(vv.y);
            vv.z = cvt_tf32(vv.z); vv.w = cvt_tf32(vv.w);
            *(float4*)&Vs[r * 136 + c4] = vv;
        }
        if (tid < 64) maskS[tid] = mb[k0 + tid];
        __syncthreads();

        // QK^T
        float sc[4][4];
#pragma unroll
        for (int nt = 0; nt < 4; nt++)
#pragma unroll
            for (int q = 0; q < 4; q++) sc[nt][q] = 0.f;

#pragma unroll 4
        for (int ks = 0; ks < 16; ks++) {
            float4 af = *(const float4*)&Qf[((wqm + ks) * 32 + lane) * 4];
            uint32_t a0 = __float_as_uint(af.x), a1 = __float_as_uint(af.y);
            uint32_t a2 = __float_as_uint(af.z), a3 = __float_as_uint(af.w);
#pragma unroll
            for (int nt = 0; nt < 4; nt++) {
                int key = wn * 32 + nt * 8 + gid;
                uint32_t b0 = __float_as_uint(KPs[key * 132 + ks * 8 + tig]);
                uint32_t b1 = __float_as_uint(KPs[key * 132 + ks * 8 + tig + 4]);
                mma_tf32_16x8x8(sc[nt], a0, a1, a2, a3, b0, b1);
            }
        }

        // Mask + scale + per-row partial max
        float m1 = -3.402823466e38f, m2 = -3.402823466e38f;
#pragma unroll
        for (int nt = 0; nt < 4; nt++) {
#pragma unroll
            for (int jj = 0; jj < 2; jj++) {
                int jloc = wn * 32 + nt * 8 + tig * 2 + jj;
                int jg = k0 + jloc;
                bool ok = (maskS[jloc] != 0);
                float s0 = (ok && jg <= q0 + r1) ? sc[nt][jj] * SCALE : NEGV;
                float s1 = (ok && jg <= q0 + r2) ? sc[nt][2 + jj] * SCALE : NEGV;
                sc[nt][jj] = s0; sc[nt][2 + jj] = s1;
                m1 = fmaxf(m1, s0); m2 = fmaxf(m2, s1);
            }
        }
        m1 = fmaxf(m1, __shfl_xor_sync(0xffffffffu, m1, 1));
        m1 = fmaxf(m1, __shfl_xor_sync(0xffffffffu, m1, 2));
        m2 = fmaxf(m2, __shfl_xor_sync(0xffffffffu, m2, 1));
        m2 = fmaxf(m2, __shfl_xor_sync(0xffffffffu, m2, 2));
        if (tig == 0) { pmx[wn * 64 + r1] = m1; pmx[wn * 64 + r2] = m2; }
        __syncthreads();  // pmx ready; all K reads done -> KPs reusable for P

        float mn1 = fmaxf(rowm[r1], fmaxf(pmx[r1], pmx[64 + r1]));
        float mn2 = fmaxf(rowm[r2], fmaxf(pmx[r2], pmx[64 + r2]));
        float l1 = 0.f, l2 = 0.f;
#pragma unroll
        for (int nt = 0; nt < 4; nt++) {
            float p00 = fexp(sc[nt][0] - mn1), p01 = fexp(sc[nt][1] - mn1);
            float p10 = fexp(sc[nt][2] - mn2), p11 = fexp(sc[nt][3] - mn2);
            l1 += p00 + p01; l2 += p10 + p11;
            int cb = wn * 32 + nt * 8 + tig * 2;
            *(float2*)&KPs[r1 * 68 + cb] = make_float2(cvt_tf32(p00), cvt_tf32(p01));
            *(float2*)&KPs[r2 * 68 + cb] = make_float2(cvt_tf32(p10), cvt_tf32(p11));
        }
        l1 += __shfl_xor_sync(0xffffffffu, l1, 1);
        l1 += __shfl_xor_sync(0xffffffffu, l1, 2);
        l2 += __shfl_xor_sync(0xffffffffu, l2, 1);
        l2 += __shfl_xor_sync(0xffffffffu, l2, 2);
        if (tig == 0) { pls[wn * 64 + r1] = l1; pls[wn * 64 + r2] = l2; }
        __syncthreads();  // pls + P stores visible

        if (tid < 64) {
            float mo = rowm[tid];
            float mn = fmaxf(mo, fmaxf(pmx[tid], pmx[64 + tid]));
            float corr = fexp(mo - mn);
            rowc[tid] = corr;
            rowm[tid] = mn;
            rowl[tid] = rowl[tid] * corr + pls[tid] + pls[64 + tid];
        }
        __syncthreads();  // rowc ready

        // PV: rescale then accumulate
        float c1 = rowc[r1], c2 = rowc[r2];
#pragma unroll
        for (int nt = 0; nt < 8; nt++) {
            o[nt][0] *= c1; o[nt][1] *= c1; o[nt][2] *= c2; o[nt][3] *= c2;
        }
#pragma unroll
        for (int ks2 = 0; ks2 < 8; ks2++) {
            uint32_t a0 = __float_as_uint(KPs[r1 * 68 + ks2 * 8 + tig]);
            uint32_t a1 = __float_as_uint(KPs[r2 * 68 + ks2 * 8 + tig]);
            uint32_t a2 = __float_as_uint(KPs[r1 * 68 + ks2 * 8 + tig + 4]);
            uint32_t a3 = __float_as_uint(KPs[r2 * 68 + ks2 * 8 + tig + 4]);
#pragma unroll
            for (int nt = 0; nt < 8; nt++) {
                int d = wd + nt * 8 + gid;
                uint32_t b0 = __float_as_uint(Vs[(ks2 * 8 + tig) * 136 + d]);
                uint32_t b1 = __float_as_uint(Vs[(ks2 * 8 + tig + 4) * 136 + d]);
                mma_tf32_16x8x8(o[nt], a0, a1, a2, a3, b0, b1);
            }
        }
    }

    // Epilogue
    float inv1 = 1.f / rowl[r1], inv2 = 1.f / rowl[r2];
    bool dead1 = rowm[r1] < -1e8f, dead2 = rowm[r2] < -1e8f;
    const float* vm = vmean + ((size_t)b * HDIM + h) * DKDIM;
    float* O1 = Og + ((size_t)b * SDIM + q0 + r1) * DDIM + h * DKDIM;
    float* O2 = Og + ((size_t)b * SDIM + q0 + r2) * DDIM + h * DKDIM;
#pragma unroll
    for (int nt = 0; nt < 8; nt++) {
        int d = wd + nt * 8 + tig * 2;
        float2 u1 = dead1 ? make_float2(vm[d], vm[d + 1])
                          : make_float2(o[nt][0] * inv1, o[nt][1] * inv1);
        float2 u2 = dead2 ? make_float2(vm[d], vm[d + 1])
                          : make_float2(o[nt][2] * inv2, o[nt][3] * inv2);
        *(float2*)(O1 + d) = u1;
        *(float2*)(O2 + d) = u2;
    }
}

// ---------------------------------------------------------------------------
extern "C" void kernel_launch(void* const* d_in, const int* in_sizes, int n_in,
                              void* d_out, int out_size)
{
    const float* x    = (const float*)d_in[0];
    const int*   mask = (const int*)d_in[1];
    const float* wq   = (const float*)d_in[2];
    const float* wk   = (const float*)d_in[3];
    const float* wv   = (const float*)d_in[4];
    const float* wo   = (const float*)d_in[5];
    float* out = (float*)d_out;

    float *pQ, *pK, *pV, *pAtt, *pVm;
    cudaGetSymbolAddress((void**)&pQ, g_Q);
    cudaGetSymbolAddress((void**)&pK, g_K);
    cudaGetSymbolAddress((void**)&pV, g_V);
    cudaGetSymbolAddress((void**)&pAtt, g_att);
    cudaGetSymbolAddress((void**)&pVm, g_vmean);

    cudaFuncSetAttribute(attn_mma_kernel, cudaFuncAttributeMaxDynamicSharedMemorySize,
                         ATT_SMEM_BYTES);

    dim3 gg(GN / 128, MDIM / 128);  // (16, 64)
    gemm_mma_kernel<<<gg, 256>>>(x, wq, pQ);
    gemm_mma_kernel<<<gg, 256>>>(x, wk, pK);
    gemm_mma_kernel<<<gg, 256>>>(x, wv, pV);

    vmean_kernel<<<BDIM * HDIM, DKDIM>>>(pV, pVm);

    attn_mma_kernel<<<dim3(SDIM / 64, HDIM, BDIM), 256, ATT_SMEM_BYTES>>>(
        pQ, pK, pV, mask, pVm, pAtt);

    gemm_mma_kernel<<<gg, 256>>>(pAtt, wo, out);
}